// round 14
// baseline (speedup 1.0000x reference)
#include <cuda_runtime.h>
#include <cuda_fp16.h>
#include <stdint.h>

#define NVOX 65536
#define KTAP 27
#define CH   64
#define TPB  256
#define EPSV 1e-5f

// ---- SMEM per pipeline buffer: A(fp16) 16KB | W(fp16) 8KB ----
#define OFF_A   0
#define OFF_W   16384
#define BUFSZ   24576
#define SMEM_TOTAL (2 * BUFSZ)     // 49152 B -> 4 CTAs/SM (single wave: 592 >= 512)

// ---------------- scratch (no allocations allowed) ----------------
__device__ float   g_h[NVOX * CH];               // conv output (fp32)
__device__ __half  g_xh[NVOX * CH];              // x as fp16
__device__ __half  g_ah[NVOX * CH];              // activations as fp16
__device__ __half  g_wt[2 * KTAP * CH * CH];     // W^T fp16: [w][k][d][c]
__device__ float   g_part[512 * 2 * CH];         // per-conv-CTA {sum, sumsq}[64]
__device__ float   g_part2[32 * 2 * CH];         // stage-1 reduced partials
__device__ float   g_sb[2 * CH];                 // folded BN affine

// ================= PTX helpers =================
__device__ __forceinline__ uint32_t smem_u32(const void* p) {
    uint32_t a;
    asm("{ .reg .u64 t; cvta.to.shared.u64 t, %1; cvt.u32.u64 %0, t; }"
        : "=r"(a) : "l"(p));
    return a;
}
__device__ __forceinline__ void cpa16(uint32_t dst, const void* src, uint32_t srcsz) {
    asm volatile("cp.async.ca.shared.global [%0], [%1], 16, %2;"
                 :: "r"(dst), "l"(src), "r"(srcsz) : "memory");
}
#define CPA_COMMIT() asm volatile("cp.async.commit_group;" ::: "memory")
#define CPA_WAIT1()  asm volatile("cp.async.wait_group 1;" ::: "memory")
#define CPA_WAIT0()  asm volatile("cp.async.wait_group 0;" ::: "memory")

#define LDSM4(r0, r1, r2, r3, addr) \
    asm volatile("ldmatrix.sync.aligned.m8n8.x4.shared.b16 {%0,%1,%2,%3}, [%4];" \
                 : "=r"(r0), "=r"(r1), "=r"(r2), "=r"(r3) : "r"(addr))

#define MMA16816(c, a, b0, b1) \
    asm volatile("mma.sync.aligned.m16n8k16.row.col.f32.f16.f16.f32 " \
                 "{%0,%1,%2,%3}, {%4,%5,%6,%7}, {%8,%9}, {%0,%1,%2,%3};" \
                 : "+f"((c)[0]), "+f"((c)[1]), "+f"((c)[2]), "+f"((c)[3]) \
                 : "r"((a)[0]), "r"((a)[1]), "r"((a)[2]), "r"((a)[3]), \
                   "r"(b0), "r"(b1))

// ================= conv via mma.sync fp16 (single product) =================
// CTA: 128 threads / 4 warps, one 128-voxel tile, full N=64; 4 CTAs/SM.
// nbr indices for the NEXT stage are prefetched into registers one tap ahead,
// so the post-barrier stage issues its cp.async immediately (no 250-cyc LDG
// dependency stall). SW128 swizzle: (row,col) -> row*128 + (col ^ ((row&7)<<4)).
// Epilogue fuses BN stats into deterministic per-block partials.
__global__ void __launch_bounds__(128, 4)
conv_mma_kernel(const __half* __restrict__ fh,
                const int* __restrict__ nbr,
                const __half* __restrict__ wt,
                float* __restrict__ out,
                float* __restrict__ part)
{
    extern __shared__ char smem[];
    const uint32_t sbase = smem_u32(smem);
    const int tid  = threadIdx.x;
    const int wid  = tid >> 5, lane = tid & 31;
    const int v0   = blockIdx.x * 128;
    const int rsub = tid >> 3;            // 0..15
    const int chnk = tid & 7;             // 0..7
    const uint32_t st_csw = (uint32_t)((chnk * 16) ^ ((rsub & 7) << 4));

    int pidx[8];                          // prefetched nbr indices for next stage
    auto loadIdx = [&](int k) {
#pragma unroll
        for (int i = 0; i < 8; ++i)
            pidx[i] = nbr[(v0 + rsub + i * 16) * KTAP + k];
    };

    // ---- stage tap k into buffer b using prefetched indices ----
    auto stage = [&](int b, int k) {
        const uint32_t base = sbase + (uint32_t)b * BUFSZ;
#pragma unroll
        for (int i = 0; i < 8; ++i) {
            const int row = rsub + i * 16;
            const int idx = pidx[i];
            const uint32_t sz = (idx >= 0) ? 16u : 0u;
            const int ic = (idx >= 0) ? idx : 0;
            const char* s = (const char*)fh + (size_t)ic * 128 + chnk * 16;
            cpa16(base + OFF_A + (uint32_t)(row * 128) + st_csw, s, sz);
        }
        const char* ws = (const char*)wt + (size_t)k * 8192;
#pragma unroll
        for (int i = 0; i < 4; ++i) {
            const int row = rsub + i * 16;            // 0..63
            cpa16(base + OFF_W + (uint32_t)(row * 128) + st_csw,
                  ws + row * 128 + chnk * 16, 16);
        }
    };

    float acc[2][8][4];
#pragma unroll
    for (int mt = 0; mt < 2; ++mt)
#pragma unroll
        for (int nt = 0; nt < 8; ++nt)
#pragma unroll
            for (int r = 0; r < 4; ++r) acc[mt][nt][r] = 0.0f;

    // ldmatrix lane->address pieces (swizzled)
    const uint32_t lxor   = (uint32_t)((lane & 7) << 4);
    const uint32_t a_rowb = (uint32_t)((wid * 32 + (lane & 15)) * 128);
    const uint32_t a_colb = (uint32_t)((lane >> 4) * 16);
    const int g = lane >> 3;
    const uint32_t b_rowb = (uint32_t)((((g >> 1) * 8) + (lane & 7)) * 128);
    const uint32_t b_colb = (uint32_t)((g & 1) * 16);

    loadIdx(0);
    stage(0, 0);
    CPA_COMMIT();
    loadIdx(1);                           // prefetch for tap-1 stage

    for (int k = 0; k < KTAP; ++k) {
        const int b = k & 1;
        if (k + 1 < KTAP) {
            stage(b ^ 1, k + 1);          // uses pidx (tap k+1)
            CPA_COMMIT();
            CPA_WAIT1();
            if (k + 2 < KTAP) loadIdx(k + 2);   // lands during compute(k)
        } else {
            CPA_WAIT0();
        }
        __syncthreads();

        const uint32_t base = sbase + (uint32_t)b * BUFSZ;
#pragma unroll
        for (int ks = 0; ks < 4; ++ks) {
            const uint32_t a_csw = (uint32_t)(ks * 32 + a_colb) ^ lxor;
            const uint32_t b_csw = (uint32_t)(ks * 32 + b_colb) ^ lxor;
            uint32_t ah[2][4];
#pragma unroll
            for (int mt = 0; mt < 2; ++mt) {
                const uint32_t aaddr = base + OFF_A + a_rowb
                                     + (uint32_t)(mt * 2048) + a_csw;
                LDSM4(ah[mt][0], ah[mt][1], ah[mt][2], ah[mt][3], aaddr);
            }
#pragma unroll
            for (int nt2 = 0; nt2 < 4; ++nt2) {
                const uint32_t baddr = base + OFF_W + b_rowb
                                     + (uint32_t)(nt2 * 2048) + b_csw;
                uint32_t bh[4];
                LDSM4(bh[0], bh[1], bh[2], bh[3], baddr);
#pragma unroll
                for (int mt = 0; mt < 2; ++mt) {
                    MMA16816(acc[mt][nt2 * 2 + 0], ah[mt], bh[0], bh[1]);
                    MMA16816(acc[mt][nt2 * 2 + 1], ah[mt], bh[2], bh[3]);
                }
            }
        }
        __syncthreads();
    }

    // ---- epilogue 1: store result tile ----
    const int r0 = v0 + wid * 32 + (lane >> 2);
    const int c0 = (lane & 3) * 2;
#pragma unroll
    for (int mt = 0; mt < 2; ++mt)
#pragma unroll
        for (int nt = 0; nt < 8; ++nt) {
            float* p0 = out + (size_t)(r0 + mt * 16) * CH + nt * 8 + c0;
            float* p1 = p0 + 8 * CH;
            *reinterpret_cast<float2*>(p0) = make_float2(acc[mt][nt][0], acc[mt][nt][1]);
            *reinterpret_cast<float2*>(p1) = make_float2(acc[mt][nt][2], acc[mt][nt][3]);
        }

    // ---- epilogue 2: fused BN stats ----
    float s[8][2], q[8][2];
#pragma unroll
    for (int nt = 0; nt < 8; ++nt)
#pragma unroll
        for (int j = 0; j < 2; ++j) {
            float a0 = acc[0][nt][j],     a1 = acc[0][nt][j + 2];
            float a2 = acc[1][nt][j],     a3 = acc[1][nt][j + 2];
            s[nt][j] = (a0 + a1) + (a2 + a3);
            q[nt][j] = (a0 * a0 + a1 * a1) + (a2 * a2 + a3 * a3);
        }
#pragma unroll
    for (int st = 4; st < 32; st <<= 1)
#pragma unroll
        for (int nt = 0; nt < 8; ++nt)
#pragma unroll
            for (int j = 0; j < 2; ++j) {
                s[nt][j] += __shfl_xor_sync(0xFFFFFFFFu, s[nt][j], st);
                q[nt][j] += __shfl_xor_sync(0xFFFFFFFFu, q[nt][j], st);
            }
    float* red = reinterpret_cast<float*>(smem);     // 2KB, bufs dead
    if (lane < 4) {
#pragma unroll
        for (int nt = 0; nt < 8; ++nt)
#pragma unroll
            for (int j = 0; j < 2; ++j) {
                const int c = nt * 8 + 2 * lane + j;
                red[(wid * 2 + 0) * CH + c] = s[nt][j];
                red[(wid * 2 + 1) * CH + c] = q[nt][j];
            }
    }
    __syncthreads();
    if (tid < CH) {
        float ts = 0.0f, tq = 0.0f;
#pragma unroll
        for (int w = 0; w < 4; ++w) {
            ts += red[(w * 2 + 0) * CH + tid];
            tq += red[(w * 2 + 1) * CH + tid];
        }
        part[blockIdx.x * 128 + tid]      = ts;
        part[blockIdx.x * 128 + CH + tid] = tq;
    }
}

// ================= prep (merged): x->fp16 + W transpose->fp16 =================
__global__ void prep_kernel(const float* __restrict__ x,
                            const float* __restrict__ W1,
                            const float* __restrict__ W2,
                            __half* __restrict__ xh,
                            __half* __restrict__ wt)
{
    if (blockIdx.x < 4096) {
        const int i = blockIdx.x * blockDim.x + threadIdx.x;   // float4 index
        float4 v = reinterpret_cast<const float4*>(x)[i];
        __half h[4];
        h[0] = __float2half_rn(v.x); h[1] = __float2half_rn(v.y);
        h[2] = __float2half_rn(v.z); h[3] = __float2half_rn(v.w);
        reinterpret_cast<uint2*>(xh)[i] = *reinterpret_cast<uint2*>(h);
    } else {
        const int t = (blockIdx.x - 4096) * blockDim.x + threadIdx.x;
        const int widx = t / (KTAP * CH * CH);
        const int rem  = t % (KTAP * CH * CH);
        const int k = rem / (CH * CH);
        const int d = (rem % (CH * CH)) / CH;
        const int c = rem % CH;
        const float* W = widx ? W2 : W1;
        wt[t] = __float2half_rn(W[k * CH * CH + c * CH + d]);
    }
}

// stage 1: 512 partial-rows -> 32 (grid=32 spreads LDG issue over 32 SMs)
__global__ void finalize1_kernel(const float* __restrict__ part,
                                 float* __restrict__ part2)
{
    __shared__ float4 sm[8][32];
    const int t  = threadIdx.x;           // 256
    const int c4 = t & 31;
    const int gp = t >> 5;
    const int row0 = blockIdx.x * 16;
    const float4* p4 = reinterpret_cast<const float4*>(part);
    float4 a = make_float4(0.f, 0.f, 0.f, 0.f);
#pragma unroll
    for (int r = gp; r < 16; r += 8) {
        float4 v = p4[(row0 + r) * 32 + c4];
        a.x += v.x; a.y += v.y; a.z += v.z; a.w += v.w;
    }
    sm[gp][c4] = a;
    __syncthreads();
    if (t < 32) {
        float4 r = make_float4(0.f, 0.f, 0.f, 0.f);
#pragma unroll
        for (int gg = 0; gg < 8; ++gg) {
            float4 v = sm[gg][t];
            r.x += v.x; r.y += v.y; r.z += v.z; r.w += v.w;
        }
        reinterpret_cast<float4*>(part2)[blockIdx.x * 32 + t] = r;
    }
}

// stage 2: combine 32 rows, fold BN affine
__global__ void finalize2_kernel(const float* __restrict__ part2,
                                 const float* __restrict__ gamma,
                                 const float* __restrict__ beta,
                                 float* __restrict__ sbuf)
{
    __shared__ float4 tot[32];
    const int t = threadIdx.x;            // 128
    if (t < 32) {
        const float4* p4 = reinterpret_cast<const float4*>(part2);
        float4 r = make_float4(0.f, 0.f, 0.f, 0.f);
#pragma unroll
        for (int g = 0; g < 32; ++g) {
            float4 v = p4[g * 32 + t];
            r.x += v.x; r.y += v.y; r.z += v.z; r.w += v.w;
        }
        tot[t] = r;
    }
    __syncthreads();
    if (t < 16) {                         // cols 0-15 sums, 16-31 sumsq
        float4 s = tot[t], q = tot[t + 16];
        const float inv_n = 1.0f / (float)NVOX;
        const float sv[4] = {s.x, s.y, s.z, s.w};
        const float qv[4] = {q.x, q.y, q.z, q.w};
#pragma unroll
        for (int e = 0; e < 4; ++e) {
            const int ch = t * 4 + e;
            const float mean = sv[e] * inv_n;
            const float var  = qv[e] * inv_n - mean * mean;
            const float sc   = gamma[ch] * rsqrtf(var + EPSV);
            sbuf[ch]      = sc;
            sbuf[CH + ch] = beta[ch] - mean * sc;
        }
    }
}

// a = relu(h*scale + bias) as fp16
__global__ void bnrelu_half_kernel(const float* __restrict__ hin,
                                   const float* __restrict__ sbuf,
                                   __half* __restrict__ ah)
{
    const int i  = blockIdx.x * blockDim.x + threadIdx.x;
    const int c0 = (i * 4) & 63;
    float4 vv = reinterpret_cast<const float4*>(hin)[i];
    float4 sc = reinterpret_cast<const float4*>(sbuf)[c0 >> 2];
    float4 bs = reinterpret_cast<const float4*>(sbuf + CH)[c0 >> 2];
    __half h[4];
    h[0] = __float2half_rn(fmaxf(fmaf(vv.x, sc.x, bs.x), 0.0f));
    h[1] = __float2half_rn(fmaxf(fmaf(vv.y, sc.y, bs.y), 0.0f));
    h[2] = __float2half_rn(fmaxf(fmaf(vv.z, sc.z, bs.z), 0.0f));
    h[3] = __float2half_rn(fmaxf(fmaf(vv.w, sc.w, bs.w), 0.0f));
    reinterpret_cast<uint2*>(ah)[i] = *reinterpret_cast<uint2*>(h);
}

// out = relu(h*scale + bias + x)
__global__ void final_kernel(const float* __restrict__ hin,
                             const float* __restrict__ sbuf,
                             const float* __restrict__ x,
                             float* __restrict__ out)
{
    const int i  = blockIdx.x * blockDim.x + threadIdx.x;
    const int c0 = (i * 4) & 63;
    float4 vv = reinterpret_cast<const float4*>(hin)[i];
    float4 xx = reinterpret_cast<const float4*>(x)[i];
    float4 sc = reinterpret_cast<const float4*>(sbuf)[c0 >> 2];
    float4 bs = reinterpret_cast<const float4*>(sbuf + CH)[c0 >> 2];
    float4 o;
    o.x = fmaxf(fmaf(vv.x, sc.x, bs.x) + xx.x, 0.0f);
    o.y = fmaxf(fmaf(vv.y, sc.y, bs.y) + xx.y, 0.0f);
    o.z = fmaxf(fmaf(vv.z, sc.z, bs.z) + xx.z, 0.0f);
    o.w = fmaxf(fmaf(vv.w, sc.w, bs.w) + xx.w, 0.0f);
    reinterpret_cast<float4*>(out)[i] = o;
}

// ================= launch =================
extern "C" void kernel_launch(void* const* d_in, const int* in_sizes, int n_in,
                              void* d_out, int out_size)
{
    const float* x   = (const float*)d_in[0];
    const int*   nbr = (const int*)  d_in[1];
    const float* W1  = (const float*)d_in[2];
    const float* ga1 = (const float*)d_in[3];
    const float* be1 = (const float*)d_in[4];
    const float* W2  = (const float*)d_in[5];
    const float* ga2 = (const float*)d_in[6];
    const float* be2 = (const float*)d_in[7];
    float* out = (float*)d_out;

    void *ph, *pxh, *pah, *pw, *pp, *pp2, *ps;
    cudaGetSymbolAddress(&ph,  g_h);
    cudaGetSymbolAddress(&pxh, g_xh);
    cudaGetSymbolAddress(&pah, g_ah);
    cudaGetSymbolAddress(&pw,  g_wt);
    cudaGetSymbolAddress(&pp,  g_part);
    cudaGetSymbolAddress(&pp2, g_part2);
    cudaGetSymbolAddress(&ps,  g_sb);
    float*  hbuf  = (float*)ph;
    __half* xh    = (__half*)pxh;
    __half* ah    = (__half*)pah;
    __half* wt    = (__half*)pw;
    float*  part  = (float*)pp;
    float*  part2 = (float*)pp2;
    float*  sbuf  = (float*)ps;

    cudaFuncSetAttribute(conv_mma_kernel,
                         cudaFuncAttributeMaxDynamicSharedMemorySize, SMEM_TOTAL);

    const int ew_grid = (NVOX * CH / 4) / TPB;              // 4096
    const int pw_grid = (2 * KTAP * CH * CH) / TPB;         // 864
    const int cv_grid = NVOX / 128;                         // 512
    const int WOFF    = KTAP * CH * CH;                     // 110592

    prep_kernel<<<ew_grid + pw_grid, TPB>>>(x, W1, W2, xh, wt);

    // h1 = conv(x, W1) with fused stats; a1 = relu(bn1(h1)) as fp16
    conv_mma_kernel<<<cv_grid, 128, SMEM_TOTAL>>>(xh, nbr, wt, hbuf, part);
    finalize1_kernel<<<32, TPB>>>(part, part2);
    finalize2_kernel<<<1, 128>>>(part2, ga1, be1, sbuf);
    bnrelu_half_kernel<<<ew_grid, TPB>>>(hbuf, sbuf, ah);

    // h2 = conv(a1, W2) with fused stats; out = relu(bn2(h2) + x)
    conv_mma_kernel<<<cv_grid, 128, SMEM_TOTAL>>>(ah, nbr, wt + WOFF, hbuf, part);
    finalize1_kernel<<<32, TPB>>>(part, part2);
    finalize2_kernel<<<1, 128>>>(part2, ga2, be2, sbuf);
    final_kernel<<<ew_grid, TPB>>>(hbuf, sbuf, x, out);
}

// round 15
// speedup vs baseline: 1.0321x; 1.0321x over previous
#include <cuda_runtime.h>
#include <cuda_fp16.h>
#include <stdint.h>

#define NVOX 65536
#define KTAP 27
#define CH   64
#define TPB  256
#define EPSV 1e-5f

// ---- SMEM per pipeline buffer: A(fp16) 16KB | W(fp16) 8KB ----
#define OFF_A   0
#define OFF_W   16384
#define BUFSZ   24576
#define SMEM_TOTAL (2 * BUFSZ)     // 49152 B -> 4 CTAs/SM (single wave: 592 >= 512)

// ---------------- scratch (no allocations allowed) ----------------
__device__ float   g_h[NVOX * CH];               // conv output (fp32)
__device__ __half  g_xh[NVOX * CH];              // x as fp16
__device__ __half  g_ah[NVOX * CH];              // activations as fp16
__device__ __half  g_wt[2 * KTAP * CH * CH];     // W^T fp16: [w][k][d][c]
__device__ float   g_part[512 * 2 * CH];         // per-conv-CTA {sum, sumsq}[64]
__device__ float   g_part2[16 * 2 * CH];         // stage-1 reduced partials
__device__ float   g_sb[2 * CH];                 // folded BN affine

// ================= PTX helpers =================
__device__ __forceinline__ uint32_t smem_u32(const void* p) {
    uint32_t a;
    asm("{ .reg .u64 t; cvta.to.shared.u64 t, %1; cvt.u32.u64 %0, t; }"
        : "=r"(a) : "l"(p));
    return a;
}
__device__ __forceinline__ void cpa16(uint32_t dst, const void* src, uint32_t srcsz) {
    asm volatile("cp.async.ca.shared.global [%0], [%1], 16, %2;"
                 :: "r"(dst), "l"(src), "r"(srcsz) : "memory");
}
#define CPA_COMMIT() asm volatile("cp.async.commit_group;" ::: "memory")
#define CPA_WAIT1()  asm volatile("cp.async.wait_group 1;" ::: "memory")
#define CPA_WAIT0()  asm volatile("cp.async.wait_group 0;" ::: "memory")

#define LDSM4(r0, r1, r2, r3, addr) \
    asm volatile("ldmatrix.sync.aligned.m8n8.x4.shared.b16 {%0,%1,%2,%3}, [%4];" \
                 : "=r"(r0), "=r"(r1), "=r"(r2), "=r"(r3) : "r"(addr))

#define MMA16816(c, a, b0, b1) \
    asm volatile("mma.sync.aligned.m16n8k16.row.col.f32.f16.f16.f32 " \
                 "{%0,%1,%2,%3}, {%4,%5,%6,%7}, {%8,%9}, {%0,%1,%2,%3};" \
                 : "+f"((c)[0]), "+f"((c)[1]), "+f"((c)[2]), "+f"((c)[3]) \
                 : "r"((a)[0]), "r"((a)[1]), "r"((a)[2]), "r"((a)[3]), \
                   "r"(b0), "r"(b1))

// ================= conv via mma.sync fp16 (single product) =================
// CTA: 128 threads / 4 warps, one 128-voxel tile, full N=64; 4 CTAs/SM.
// Measured: this kernel runs at ~92% of the HMMA.16816 issue floor
// (rt ~16 cyc/SMSP on sm_103 legacy mma.sync path) — it IS the floor.
// SW128 swizzle: (row,col) -> row*128 + (col ^ ((row&7)<<4)).
// Epilogue fuses BN stats into deterministic per-block partials.
__global__ void __launch_bounds__(128, 4)
conv_mma_kernel(const __half* __restrict__ fh,
                const int* __restrict__ nbr,
                const __half* __restrict__ wt,
                float* __restrict__ out,
                float* __restrict__ part)
{
    extern __shared__ char smem[];
    const uint32_t sbase = smem_u32(smem);
    const int tid  = threadIdx.x;
    const int wid  = tid >> 5, lane = tid & 31;
    const int v0   = blockIdx.x * 128;
    const int rsub = tid >> 3;            // 0..15
    const int chnk = tid & 7;             // 0..7
    const uint32_t st_csw = (uint32_t)((chnk * 16) ^ ((rsub & 7) << 4));

    // ---- stage tap k into buffer b ----
    auto stage = [&](int b, int k) {
        const uint32_t base = sbase + (uint32_t)b * BUFSZ;
#pragma unroll
        for (int i = 0; i < 8; ++i) {
            const int row = rsub + i * 16;
            const int idx = nbr[(v0 + row) * KTAP + k];
            const uint32_t sz = (idx >= 0) ? 16u : 0u;
            const int ic = (idx >= 0) ? idx : 0;
            const char* s = (const char*)fh + (size_t)ic * 128 + chnk * 16;
            cpa16(base + OFF_A + (uint32_t)(row * 128) + st_csw, s, sz);
        }
        const char* ws = (const char*)wt + (size_t)k * 8192;
#pragma unroll
        for (int i = 0; i < 4; ++i) {
            const int row = rsub + i * 16;            // 0..63
            cpa16(base + OFF_W + (uint32_t)(row * 128) + st_csw,
                  ws + row * 128 + chnk * 16, 16);
        }
    };

    float acc[2][8][4];
#pragma unroll
    for (int mt = 0; mt < 2; ++mt)
#pragma unroll
        for (int nt = 0; nt < 8; ++nt)
#pragma unroll
            for (int r = 0; r < 4; ++r) acc[mt][nt][r] = 0.0f;

    // ldmatrix lane->address pieces (swizzled)
    const uint32_t lxor   = (uint32_t)((lane & 7) << 4);
    const uint32_t a_rowb = (uint32_t)((wid * 32 + (lane & 15)) * 128);
    const uint32_t a_colb = (uint32_t)((lane >> 4) * 16);
    const int g = lane >> 3;
    const uint32_t b_rowb = (uint32_t)((((g >> 1) * 8) + (lane & 7)) * 128);
    const uint32_t b_colb = (uint32_t)((g & 1) * 16);

    stage(0, 0);
    CPA_COMMIT();

    for (int k = 0; k < KTAP; ++k) {
        const int b = k & 1;
        if (k + 1 < KTAP) { stage(b ^ 1, k + 1); CPA_COMMIT(); CPA_WAIT1(); }
        else              { CPA_WAIT0(); }
        __syncthreads();

        const uint32_t base = sbase + (uint32_t)b * BUFSZ;
#pragma unroll
        for (int ks = 0; ks < 4; ++ks) {
            const uint32_t a_csw = (uint32_t)(ks * 32 + a_colb) ^ lxor;
            const uint32_t b_csw = (uint32_t)(ks * 32 + b_colb) ^ lxor;
            uint32_t ah[2][4];
#pragma unroll
            for (int mt = 0; mt < 2; ++mt) {
                const uint32_t aaddr = base + OFF_A + a_rowb
                                     + (uint32_t)(mt * 2048) + a_csw;
                LDSM4(ah[mt][0], ah[mt][1], ah[mt][2], ah[mt][3], aaddr);
            }
#pragma unroll
            for (int nt2 = 0; nt2 < 4; ++nt2) {
                const uint32_t baddr = base + OFF_W + b_rowb
                                     + (uint32_t)(nt2 * 2048) + b_csw;
                uint32_t bh[4];
                LDSM4(bh[0], bh[1], bh[2], bh[3], baddr);
#pragma unroll
                for (int mt = 0; mt < 2; ++mt) {
                    MMA16816(acc[mt][nt2 * 2 + 0], ah[mt], bh[0], bh[1]);
                    MMA16816(acc[mt][nt2 * 2 + 1], ah[mt], bh[2], bh[3]);
                }
            }
        }
        __syncthreads();
    }

    // ---- epilogue 1: store result tile ----
    const int r0 = v0 + wid * 32 + (lane >> 2);
    const int c0 = (lane & 3) * 2;
#pragma unroll
    for (int mt = 0; mt < 2; ++mt)
#pragma unroll
        for (int nt = 0; nt < 8; ++nt) {
            float* p0 = out + (size_t)(r0 + mt * 16) * CH + nt * 8 + c0;
            float* p1 = p0 + 8 * CH;
            *reinterpret_cast<float2*>(p0) = make_float2(acc[mt][nt][0], acc[mt][nt][1]);
            *reinterpret_cast<float2*>(p1) = make_float2(acc[mt][nt][2], acc[mt][nt][3]);
        }

    // ---- epilogue 2: fused BN stats ----
    float s[8][2], q[8][2];
#pragma unroll
    for (int nt = 0; nt < 8; ++nt)
#pragma unroll
        for (int j = 0; j < 2; ++j) {
            float a0 = acc[0][nt][j],     a1 = acc[0][nt][j + 2];
            float a2 = acc[1][nt][j],     a3 = acc[1][nt][j + 2];
            s[nt][j] = (a0 + a1) + (a2 + a3);
            q[nt][j] = (a0 * a0 + a1 * a1) + (a2 * a2 + a3 * a3);
        }
#pragma unroll
    for (int st = 4; st < 32; st <<= 1)
#pragma unroll
        for (int nt = 0; nt < 8; ++nt)
#pragma unroll
            for (int j = 0; j < 2; ++j) {
                s[nt][j] += __shfl_xor_sync(0xFFFFFFFFu, s[nt][j], st);
                q[nt][j] += __shfl_xor_sync(0xFFFFFFFFu, q[nt][j], st);
            }
    float* red = reinterpret_cast<float*>(smem);     // 2KB, bufs dead
    if (lane < 4) {
#pragma unroll
        for (int nt = 0; nt < 8; ++nt)
#pragma unroll
            for (int j = 0; j < 2; ++j) {
                const int c = nt * 8 + 2 * lane + j;
                red[(wid * 2 + 0) * CH + c] = s[nt][j];
                red[(wid * 2 + 1) * CH + c] = q[nt][j];
            }
    }
    __syncthreads();
    if (tid < CH) {
        float ts = 0.0f, tq = 0.0f;
#pragma unroll
        for (int w = 0; w < 4; ++w) {
            ts += red[(w * 2 + 0) * CH + tid];
            tq += red[(w * 2 + 1) * CH + tid];
        }
        part[blockIdx.x * 128 + tid]      = ts;
        part[blockIdx.x * 128 + CH + tid] = tq;
    }
}

// ================= prep (merged): x->fp16 + W transpose->fp16 =================
__global__ void prep_kernel(const float* __restrict__ x,
                            const float* __restrict__ W1,
                            const float* __restrict__ W2,
                            __half* __restrict__ xh,
                            __half* __restrict__ wt)
{
    if (blockIdx.x < 4096) {
        const int i = blockIdx.x * blockDim.x + threadIdx.x;   // float4 index
        float4 v = reinterpret_cast<const float4*>(x)[i];
        __half h[4];
        h[0] = __float2half_rn(v.x); h[1] = __float2half_rn(v.y);
        h[2] = __float2half_rn(v.z); h[3] = __float2half_rn(v.w);
        reinterpret_cast<uint2*>(xh)[i] = *reinterpret_cast<uint2*>(h);
    } else {
        const int t = (blockIdx.x - 4096) * blockDim.x + threadIdx.x;
        const int widx = t / (KTAP * CH * CH);
        const int rem  = t % (KTAP * CH * CH);
        const int k = rem / (CH * CH);
        const int d = (rem % (CH * CH)) / CH;
        const int c = rem % CH;
        const float* W = widx ? W2 : W1;
        wt[t] = __float2half_rn(W[k * CH * CH + c * CH + d]);
    }
}

// stage 1: 512 partial-rows -> 16 (grid=16: 32 rows/block, 4 indep loads/thread)
__global__ void finalize1_kernel(const float* __restrict__ part,
                                 float* __restrict__ part2)
{
    __shared__ float4 sm[8][32];
    const int t  = threadIdx.x;           // 256
    const int c4 = t & 31;
    const int gp = t >> 5;
    const int row0 = blockIdx.x * 32;
    const float4* p4 = reinterpret_cast<const float4*>(part);
    float4 a = make_float4(0.f, 0.f, 0.f, 0.f);
#pragma unroll
    for (int r = gp; r < 32; r += 8) {
        float4 v = p4[(row0 + r) * 32 + c4];
        a.x += v.x; a.y += v.y; a.z += v.z; a.w += v.w;
    }
    sm[gp][c4] = a;
    __syncthreads();
    if (t < 32) {
        float4 r = make_float4(0.f, 0.f, 0.f, 0.f);
#pragma unroll
        for (int gg = 0; gg < 8; ++gg) {
            float4 v = sm[gg][t];
            r.x += v.x; r.y += v.y; r.z += v.z; r.w += v.w;
        }
        reinterpret_cast<float4*>(part2)[blockIdx.x * 32 + t] = r;
    }
}

// stage 2: combine 16 rows (parallel 8-group shape, 2 loads/thread), fold affine
__global__ void finalize2_kernel(const float* __restrict__ part2,
                                 const float* __restrict__ gamma,
                                 const float* __restrict__ beta,
                                 float* __restrict__ sbuf)
{
    __shared__ float4 sm[8][32];
    const int t  = threadIdx.x;           // 256
    const int c4 = t & 31;
    const int gp = t >> 5;
    const float4* p4 = reinterpret_cast<const float4*>(part2);
    float4 a = make_float4(0.f, 0.f, 0.f, 0.f);
#pragma unroll
    for (int r = gp; r < 16; r += 8) {
        float4 v = p4[r * 32 + c4];
        a.x += v.x; a.y += v.y; a.z += v.z; a.w += v.w;
    }
    sm[gp][c4] = a;
    __syncthreads();
    __shared__ float4 tot[32];
    if (t < 32) {
        float4 r = make_float4(0.f, 0.f, 0.f, 0.f);
#pragma unroll
        for (int gg = 0; gg < 8; ++gg) {
            float4 v = sm[gg][t];
            r.x += v.x; r.y += v.y; r.z += v.z; r.w += v.w;
        }
        tot[t] = r;
    }
    __syncthreads();
    if (t < 16) {                         // cols 0-15 sums, 16-31 sumsq
        float4 s = tot[t], q = tot[t + 16];
        const float inv_n = 1.0f / (float)NVOX;
        const float sv[4] = {s.x, s.y, s.z, s.w};
        const float qv[4] = {q.x, q.y, q.z, q.w};
#pragma unroll
        for (int e = 0; e < 4; ++e) {
            const int ch = t * 4 + e;
            const float mean = sv[e] * inv_n;
            const float var  = qv[e] * inv_n - mean * mean;
            const float sc   = gamma[ch] * rsqrtf(var + EPSV);
            sbuf[ch]      = sc;
            sbuf[CH + ch] = beta[ch] - mean * sc;
        }
    }
}

// a = relu(h*scale + bias) as fp16
__global__ void bnrelu_half_kernel(const float* __restrict__ hin,
                                   const float* __restrict__ sbuf,
                                   __half* __restrict__ ah)
{
    const int i  = blockIdx.x * blockDim.x + threadIdx.x;
    const int c0 = (i * 4) & 63;
    float4 vv = reinterpret_cast<const float4*>(hin)[i];
    float4 sc = reinterpret_cast<const float4*>(sbuf)[c0 >> 2];
    float4 bs = reinterpret_cast<const float4*>(sbuf + CH)[c0 >> 2];
    __half h[4];
    h[0] = __float2half_rn(fmaxf(fmaf(vv.x, sc.x, bs.x), 0.0f));
    h[1] = __float2half_rn(fmaxf(fmaf(vv.y, sc.y, bs.y), 0.0f));
    h[2] = __float2half_rn(fmaxf(fmaf(vv.z, sc.z, bs.z), 0.0f));
    h[3] = __float2half_rn(fmaxf(fmaf(vv.w, sc.w, bs.w), 0.0f));
    reinterpret_cast<uint2*>(ah)[i] = *reinterpret_cast<uint2*>(h);
}

// out = relu(h*scale + bias + x)
__global__ void final_kernel(const float* __restrict__ hin,
                             const float* __restrict__ sbuf,
                             const float* __restrict__ x,
                             float* __restrict__ out)
{
    const int i  = blockIdx.x * blockDim.x + threadIdx.x;
    const int c0 = (i * 4) & 63;
    float4 vv = reinterpret_cast<const float4*>(hin)[i];
    float4 xx = reinterpret_cast<const float4*>(x)[i];
    float4 sc = reinterpret_cast<const float4*>(sbuf)[c0 >> 2];
    float4 bs = reinterpret_cast<const float4*>(sbuf + CH)[c0 >> 2];
    float4 o;
    o.x = fmaxf(fmaf(vv.x, sc.x, bs.x) + xx.x, 0.0f);
    o.y = fmaxf(fmaf(vv.y, sc.y, bs.y) + xx.y, 0.0f);
    o.z = fmaxf(fmaf(vv.z, sc.z, bs.z) + xx.z, 0.0f);
    o.w = fmaxf(fmaf(vv.w, sc.w, bs.w) + xx.w, 0.0f);
    reinterpret_cast<float4*>(out)[i] = o;
}

// ================= launch =================
extern "C" void kernel_launch(void* const* d_in, const int* in_sizes, int n_in,
                              void* d_out, int out_size)
{
    const float* x   = (const float*)d_in[0];
    const int*   nbr = (const int*)  d_in[1];
    const float* W1  = (const float*)d_in[2];
    const float* ga1 = (const float*)d_in[3];
    const float* be1 = (const float*)d_in[4];
    const float* W2  = (const float*)d_in[5];
    const float* ga2 = (const float*)d_in[6];
    const float* be2 = (const float*)d_in[7];
    float* out = (float*)d_out;

    void *ph, *pxh, *pah, *pw, *pp, *pp2, *ps;
    cudaGetSymbolAddress(&ph,  g_h);
    cudaGetSymbolAddress(&pxh, g_xh);
    cudaGetSymbolAddress(&pah, g_ah);
    cudaGetSymbolAddress(&pw,  g_wt);
    cudaGetSymbolAddress(&pp,  g_part);
    cudaGetSymbolAddress(&pp2, g_part2);
    cudaGetSymbolAddress(&ps,  g_sb);
    float*  hbuf  = (float*)ph;
    __half* xh    = (__half*)pxh;
    __half* ah    = (__half*)pah;
    __half* wt    = (__half*)pw;
    float*  part  = (float*)pp;
    float*  part2 = (float*)pp2;
    float*  sbuf  = (float*)ps;

    cudaFuncSetAttribute(conv_mma_kernel,
                         cudaFuncAttributeMaxDynamicSharedMemorySize, SMEM_TOTAL);

    const int ew_grid = (NVOX * CH / 4) / TPB;              // 4096
    const int pw_grid = (2 * KTAP * CH * CH) / TPB;         // 864
    const int cv_grid = NVOX / 128;                         // 512
    const int WOFF    = KTAP * CH * CH;                     // 110592

    prep_kernel<<<ew_grid + pw_grid, TPB>>>(x, W1, W2, xh, wt);

    // h1 = conv(x, W1) with fused stats; a1 = relu(bn1(h1)) as fp16
    conv_mma_kernel<<<cv_grid, 128, SMEM_TOTAL>>>(xh, nbr, wt, hbuf, part);
    finalize1_kernel<<<16, TPB>>>(part, part2);
    finalize2_kernel<<<1, TPB>>>(part2, ga1, be1, sbuf);
    bnrelu_half_kernel<<<ew_grid, TPB>>>(hbuf, sbuf, ah);

    // h2 = conv(a1, W2) with fused stats; out = relu(bn2(h2) + x)
    conv_mma_kernel<<<cv_grid, 128, SMEM_TOTAL>>>(ah, nbr, wt + WOFF, hbuf, part);
    finalize1_kernel<<<16, TPB>>>(part, part2);
    finalize2_kernel<<<1, TPB>>>(part2, ga2, be2, sbuf);
    final_kernel<<<ew_grid, TPB>>>(hbuf, sbuf, x, out);
}